// round 1
// baseline (speedup 1.0000x reference)
#include <cuda_runtime.h>
#include <cstdint>

typedef unsigned long long ull;

#define TPB   512
#define NB    4
#define R_    16
#define D_    1024

// ---- packed f32x2 helpers (Blackwell sm_103a) ----
__device__ __forceinline__ ull ffma2(ull a, ull b, ull c) {
    ull d;
    asm("fma.rn.f32x2 %0, %1, %2, %3;" : "=l"(d) : "l"(a), "l"(b), "l"(c));
    return d;
}
__device__ __forceinline__ ull fmul2(ull a, ull b) {
    ull d;
    asm("mul.rn.f32x2 %0, %1, %2;" : "=l"(d) : "l"(a), "l"(b));
    return d;
}
__device__ __forceinline__ ull fadd2(ull a, ull b) {
    ull d;
    asm("add.rn.f32x2 %0, %1, %2;" : "=l"(d) : "l"(a), "l"(b));
    return d;
}
__device__ __forceinline__ float lo_(ull v) { return __int_as_float((int)(unsigned)(v & 0xffffffffull)); }
__device__ __forceinline__ float hi_(ull v) { return __int_as_float((int)(unsigned)(v >> 32)); }
__device__ __forceinline__ ull   dup_(float v) { unsigned u = __float_as_uint(v); return ((ull)u << 32) | (ull)u; }

__global__ __launch_bounds__(TPB, 1)
void rlora_kernel(const int*   __restrict__ indices,
                  const float* __restrict__ baseW,
                  const float* __restrict__ loraA,
                  const float* __restrict__ loraB,
                  float*       __restrict__ out,
                  int n_rows)
{
    __shared__ ull   sb[NB][R_];          // 0.1 * lora_B[idx][r], duplicated halves
    __shared__ int   sidx[NB];
    __shared__ float red[NB * 3][TPB];    // per-lane partials: x2, y2, xy per row
    __shared__ float rsum[NB * 3];
    __shared__ ull   scx[NB], scy[NB];    // duplicated output coefficients

    const int tid = threadIdx.x;
    const int d0  = tid * 2;              // this lane owns d0, d0+1

    // lora_A stays register-resident for the whole kernel:
    // lane owns A[r][d0:d0+2] for all 16 ranks (32 regs).
    ull a[R_];
    #pragma unroll
    for (int r = 0; r < R_; ++r)
        a[r] = __ldg(reinterpret_cast<const ull*>(loraA + r * D_ + d0));

    const int nbatch = (n_rows + NB - 1) / NB;

    for (int batch = blockIdx.x; batch < nbatch; batch += gridDim.x) {
        const int row0 = batch * NB;

        // ---- stage indices + scaled/duplicated b rows into smem ----
        if (tid < NB * R_) {
            int row = tid >> 4;
            int r   = tid & 15;
            int g   = row0 + row;
            if (g < n_rows) {
                int idx = __ldg(indices + g);
                float v = 0.1f * __ldg(loraB + (size_t)idx * R_ + r);
                sb[row][r] = dup_(v);
                if (r == 0) sidx[row] = idx;
            }
        }
        __syncthreads();

        // ---- pass: load x, compute delta, per-lane partial sums ----
        ull xv[NB], dv[NB];
        #pragma unroll
        for (int row = 0; row < NB; ++row) {
            int g = row0 + row;
            xv[row] = (g < n_rows)
                ? __ldg(reinterpret_cast<const ull*>(baseW + (size_t)sidx[row] * D_ + d0))
                : 0ull;
        }
        #pragma unroll
        for (int row = 0; row < NB; ++row) {
            ull acc0 = fmul2(sb[row][0], a[0]);
            ull acc1 = fmul2(sb[row][1], a[1]);
            #pragma unroll
            for (int r = 2; r < R_; r += 2) {
                acc0 = ffma2(sb[row][r],     a[r],     acc0);
                acc1 = ffma2(sb[row][r + 1], a[r + 1], acc1);
            }
            dv[row] = fadd2(acc0, acc1);

            float xl = lo_(xv[row]), xh = hi_(xv[row]);
            float yl = lo_(dv[row]), yh = hi_(dv[row]);
            red[row * 3 + 0][tid] = xl * xl + xh * xh;  // ||x||^2 partial
            red[row * 3 + 1][tid] = yl * yl + yh * yh;  // ||d||^2 partial
            red[row * 3 + 2][tid] = xl * yl + xh * yh;  // <x,d>  partial
        }
        __syncthreads();

        // ---- block reduce: one warp per (row, value) ----
        {
            int warp = tid >> 5, lane = tid & 31;
            if (warp < NB * 3) {
                const float* p = red[warp];
                float s = 0.f;
                #pragma unroll
                for (int k = 0; k < TPB / 32; ++k) s += p[lane + k * 32];
                #pragma unroll
                for (int off = 16; off > 0; off >>= 1)
                    s += __shfl_xor_sync(0xffffffffu, s, off);
                if (lane == 0) rsum[warp] = s;
            }
        }
        __syncthreads();

        // ---- per-row scalar epilogue (analytic clamps + Mobius) ----
        if (tid < NB) {
            const float MAXN = 1.0f - 1e-5f;
            const float EPSN = 1e-5f;
            float x2 = rsum[tid * 3 + 0];
            float y2 = rsum[tid * 3 + 1];
            float xy = rsum[tid * 3 + 2];

            float nx = sqrtf(x2);
            float sx = (nx > MAXN) ? MAXN / fmaxf(nx, EPSN) : 1.0f;
            float ny = sqrtf(y2);
            float sy = (ny > MAXN) ? MAXN / fmaxf(ny, EPSN) : 1.0f;

            float X2 = sx * sx * x2;
            float Y2 = sy * sy * y2;
            float XY = sx * sy * xy;

            float A_  = 1.0f + 2.0f * XY + Y2;
            float B_  = 1.0f - X2;
            float den = fmaxf(1.0f + 2.0f * XY + X2 * Y2, 1e-15f);

            // analytic norm of (A_*xc + B_*yc)/den
            float n2 = (A_ * A_ * X2 + 2.0f * A_ * B_ * XY + B_ * B_ * Y2) / (den * den);
            float no = sqrtf(fmaxf(n2, 0.0f));
            float sf = (no > MAXN) ? MAXN / fmaxf(no, EPSN) : 1.0f;

            float cx = sf * A_ * sx / den;
            float cy = sf * B_ * sy / den;
            scx[tid] = dup_(cx);
            scy[tid] = dup_(cy);
        }
        __syncthreads();

        // ---- write out = cx*x + cy*delta (x, delta still in registers) ----
        #pragma unroll
        for (int row = 0; row < NB; ++row) {
            int g = row0 + row;
            if (g < n_rows) {
                ull o = ffma2(scx[row], xv[row], fmul2(scy[row], dv[row]));
                *reinterpret_cast<ull*>(out + (size_t)g * D_ + d0) = o;
            }
        }
        // no trailing barrier needed: next-iter smem writes are each
        // separated from this iteration's last reads by a later barrier.
    }
}

extern "C" void kernel_launch(void* const* d_in, const int* in_sizes, int n_in,
                              void* d_out, int out_size)
{
    const int*   indices = (const int*)  d_in[0];
    const float* baseW   = (const float*)d_in[1];
    const float* loraA   = (const float*)d_in[2];
    const float* loraB   = (const float*)d_in[3];
    float*       out     = (float*)d_out;

    int n_rows = in_sizes[0];                    // 8 * 4096 = 32768
    int nbatch = (n_rows + NB - 1) / NB;
    int grid   = nbatch < 148 ? nbatch : 148;    // persistent: 1 CTA/SM

    rlora_kernel<<<grid, TPB>>>(indices, baseW, loraA, loraB, out, n_rows);
}

// round 2
// speedup vs baseline: 1.3323x; 1.3323x over previous
#include <cuda_runtime.h>
#include <cstdint>

typedef unsigned long long ull;

#define TPB   512
#define NB    4
#define R_    16
#define D_    1024

// ---- packed f32x2 helpers (Blackwell sm_103a) ----
__device__ __forceinline__ ull ffma2(ull a, ull b, ull c) {
    ull d;
    asm("fma.rn.f32x2 %0, %1, %2, %3;" : "=l"(d) : "l"(a), "l"(b), "l"(c));
    return d;
}
__device__ __forceinline__ ull fmul2(ull a, ull b) {
    ull d;
    asm("mul.rn.f32x2 %0, %1, %2;" : "=l"(d) : "l"(a), "l"(b));
    return d;
}
__device__ __forceinline__ ull fadd2(ull a, ull b) {
    ull d;
    asm("add.rn.f32x2 %0, %1, %2;" : "=l"(d) : "l"(a), "l"(b));
    return d;
}
__device__ __forceinline__ float lo_(ull v) { return __int_as_float((int)(unsigned)(v & 0xffffffffull)); }
__device__ __forceinline__ float hi_(ull v) { return __int_as_float((int)(unsigned)(v >> 32)); }
__device__ __forceinline__ ull   dup_(float v) { unsigned u = __float_as_uint(v); return ((ull)u << 32) | (ull)u; }

__device__ __forceinline__ unsigned sptr(const void* p) {
    return (unsigned)__cvta_generic_to_shared(p);
}

__global__ __launch_bounds__(TPB, 1)
void rlora_kernel(const int*   __restrict__ indices,
                  const float* __restrict__ baseW,
                  const float* __restrict__ loraA,
                  const float* __restrict__ loraB,
                  float*       __restrict__ out,
                  int n_rows, int nbatch)
{
    __shared__ ull   xbuf[2][NB][TPB];    // prefetched base rows (each thread's 8B slice)
    __shared__ ull   sb[2][NB][R_];       // 0.1 * lora_B[idx][r], duplicated halves
    __shared__ float red[NB * 3][TPB];    // per-lane partials: x2, y2, xy per row
    __shared__ ull   scx[NB], scy[NB];    // duplicated output coefficients

    const int tid = threadIdx.x;
    const int d0  = tid * 2;              // this lane owns columns d0, d0+1

    // lora_A register-resident for the whole kernel (32 regs)
    ull a[R_];
    #pragma unroll
    for (int r = 0; r < R_; ++r)
        a[r] = __ldg(reinterpret_cast<const ull*>(loraA + r * D_ + d0));

    const int stride = gridDim.x;
    const int batch0 = blockIdx.x;

    // ---------- prologue: prefetch batch0 into buffer 0 ----------
    {
        #pragma unroll
        for (int row = 0; row < NB; ++row) {
            int g = batch0 * NB + row;
            if (g < n_rows) {
                int idx = __ldg(indices + g);
                const float* src = baseW + (size_t)idx * D_ + d0;
                unsigned dst = sptr(&xbuf[0][row][tid]);
                asm volatile("cp.async.ca.shared.global [%0], [%1], 8;\n"
                             :: "r"(dst), "l"(src));
            }
        }
        asm volatile("cp.async.commit_group;\n");
        // stage sb for batch0
        if (tid < NB * R_) {
            int row = tid >> 4, r = tid & 15;
            int g = batch0 * NB + row;
            if (g < n_rows) {
                int idx = __ldg(indices + g);
                sb[0][row][r] = dup_(0.1f * __ldg(loraB + (size_t)idx * R_ + r));
            }
        }
    }
    __syncthreads();   // sb[0] visible

    int buf = 0;
    for (int batch = batch0; batch < nbatch; batch += stride, buf ^= 1) {
        const int row0 = batch * NB;
        const int nxt  = batch + stride;

        // ---- issue prefetch for NEXT batch (x via cp.async, sb staged) ----
        #pragma unroll
        for (int row = 0; row < NB; ++row) {
            int g = nxt * NB + row;
            if (nxt < nbatch && g < n_rows) {
                int idx = __ldg(indices + g);
                const float* src = baseW + (size_t)idx * D_ + d0;
                unsigned dst = sptr(&xbuf[buf ^ 1][row][tid]);
                asm volatile("cp.async.ca.shared.global [%0], [%1], 8;\n"
                             :: "r"(dst), "l"(src));
            }
        }
        asm volatile("cp.async.commit_group;\n");
        if (tid < NB * R_) {
            int row = tid >> 4, r = tid & 15;
            int g = nxt * NB + row;
            if (nxt < nbatch && g < n_rows) {
                int idx = __ldg(indices + g);
                sb[buf ^ 1][row][r] = dup_(0.1f * __ldg(loraB + (size_t)idx * R_ + r));
            }
        }

        // ---- wait for CURRENT batch's x data (keep 1 newer group in flight) ----
        asm volatile("cp.async.wait_group 1;\n" ::: "memory");

        // ---- compute delta + per-lane partial sums ----
        ull xv[NB], dv[NB];
        #pragma unroll
        for (int row = 0; row < NB; ++row)
            xv[row] = xbuf[buf][row][tid];

        #pragma unroll
        for (int row = 0; row < NB; ++row) {
            const ulonglong2* bp = reinterpret_cast<const ulonglong2*>(sb[buf][row]);
            ulonglong2 b01 = bp[0];
            ull acc0 = fmul2(b01.x, a[0]);
            ull acc1 = fmul2(b01.y, a[1]);
            #pragma unroll
            for (int k = 1; k < R_ / 2; ++k) {
                ulonglong2 b = bp[k];
                acc0 = ffma2(b.x, a[2 * k],     acc0);
                acc1 = ffma2(b.y, a[2 * k + 1], acc1);
            }
            dv[row] = fadd2(acc0, acc1);

            float xl = lo_(xv[row]), xh = hi_(xv[row]);
            float yl = lo_(dv[row]), yh = hi_(dv[row]);
            red[row * 3 + 0][tid] = fmaf(xl, xl, xh * xh);
            red[row * 3 + 1][tid] = fmaf(yl, yl, yh * yh);
            red[row * 3 + 2][tid] = fmaf(xl, yl, xh * yh);
        }
        __syncthreads();

        // ---- reduction: warp w owns row w (3 interleaved shuffle trees) ----
        {
            int warp = tid >> 5, lane = tid & 31;
            if (warp < NB) {
                const float* p0 = red[warp * 3 + 0];
                const float* p1 = red[warp * 3 + 1];
                const float* p2 = red[warp * 3 + 2];
                float s0 = 0.f, s1 = 0.f, s2 = 0.f;
                #pragma unroll
                for (int k = 0; k < TPB / 32; ++k) {
                    s0 += p0[lane + k * 32];
                    s1 += p1[lane + k * 32];
                    s2 += p2[lane + k * 32];
                }
                #pragma unroll
                for (int off = 16; off > 0; off >>= 1) {
                    s0 += __shfl_xor_sync(0xffffffffu, s0, off);
                    s1 += __shfl_xor_sync(0xffffffffu, s1, off);
                    s2 += __shfl_xor_sync(0xffffffffu, s2, off);
                }
                if (lane == 0) {
                    const float MAXN = 1.0f - 1e-5f;
                    const float EPSN = 1e-5f;
                    float x2 = s0, y2 = s1, xy = s2;

                    float nx = sqrtf(x2);
                    float sx = (nx > MAXN) ? __fdividef(MAXN, fmaxf(nx, EPSN)) : 1.0f;
                    float ny = sqrtf(y2);
                    float sy = (ny > MAXN) ? __fdividef(MAXN, fmaxf(ny, EPSN)) : 1.0f;

                    float X2 = sx * sx * x2;
                    float Y2 = sy * sy * y2;
                    float XY = sx * sy * xy;

                    float A_  = 1.0f + 2.0f * XY + Y2;
                    float B_  = 1.0f - X2;
                    float den = fmaxf(1.0f + 2.0f * XY + X2 * Y2, 1e-15f);

                    float n2 = (A_ * A_ * X2 + 2.0f * A_ * B_ * XY + B_ * B_ * Y2)
                               / (den * den);
                    float no = sqrtf(fmaxf(n2, 0.0f));
                    float sf = (no > MAXN) ? __fdividef(MAXN, fmaxf(no, EPSN)) : 1.0f;

                    float cx = __fdividef(sf * A_ * sx, den);
                    float cy = __fdividef(sf * B_ * sy, den);
                    scx[warp] = dup_(cx);
                    scy[warp] = dup_(cy);
                }
            }
        }
        __syncthreads();

        // ---- write out = cx*x + cy*delta (streaming stores) ----
        #pragma unroll
        for (int row = 0; row < NB; ++row) {
            int g = row0 + row;
            if (g < n_rows) {
                ull o = ffma2(scx[row], xv[row], fmul2(scy[row], dv[row]));
                __stcs(reinterpret_cast<ull*>(out + (size_t)g * D_ + d0), o);
            }
        }
        // next iteration's smem writes (red, sb[buf^1], cp.async slots) are each
        // separated from this iteration's final reads by barriers / same-thread order.
    }
}

extern "C" void kernel_launch(void* const* d_in, const int* in_sizes, int n_in,
                              void* d_out, int out_size)
{
    const int*   indices = (const int*)  d_in[0];
    const float* baseW   = (const float*)d_in[1];
    const float* loraA   = (const float*)d_in[2];
    const float* loraB   = (const float*)d_in[3];
    float*       out     = (float*)d_out;

    int n_rows = in_sizes[0];                    // 8 * 4096 = 32768
    int nbatch = (n_rows + NB - 1) / NB;
    int grid   = nbatch < 148 ? nbatch : 148;    // persistent: 1 CTA/SM

    rlora_kernel<<<grid, TPB>>>(indices, baseW, loraA, loraB, out, n_rows, nbatch);
}

// round 3
// speedup vs baseline: 1.4939x; 1.1213x over previous
#include <cuda_runtime.h>
#include <cstdint>

typedef unsigned long long ull;

#define TPB   512
#define NB    8
#define R_    16
#define D_    1024

// ---- packed f32x2 helpers (Blackwell sm_103a) ----
__device__ __forceinline__ ull ffma2(ull a, ull b, ull c) {
    ull d;
    asm("fma.rn.f32x2 %0, %1, %2, %3;" : "=l"(d) : "l"(a), "l"(b), "l"(c));
    return d;
}
__device__ __forceinline__ ull fmul2(ull a, ull b) {
    ull d;
    asm("mul.rn.f32x2 %0, %1, %2;" : "=l"(d) : "l"(a), "l"(b));
    return d;
}
__device__ __forceinline__ ull fadd2(ull a, ull b) {
    ull d;
    asm("add.rn.f32x2 %0, %1, %2;" : "=l"(d) : "l"(a), "l"(b));
    return d;
}
__device__ __forceinline__ float lo_(ull v) { return __int_as_float((int)(unsigned)(v & 0xffffffffull)); }
__device__ __forceinline__ float hi_(ull v) { return __int_as_float((int)(unsigned)(v >> 32)); }
__device__ __forceinline__ ull   dup_(float v) { unsigned u = __float_as_uint(v); return ((ull)u << 32) | (ull)u; }
__device__ __forceinline__ ull   pack2_(float l, float h) {
    unsigned ul = __float_as_uint(l), uh = __float_as_uint(h);
    return ((ull)uh << 32) | (ull)ul;
}

__global__ __launch_bounds__(TPB, 1)
void rlora_kernel(const int*   __restrict__ indices,
                  const float* __restrict__ baseW,
                  const float* __restrict__ loraA,
                  const float* __restrict__ loraB,
                  float*       __restrict__ out,
                  int n_rows, int nbatch)
{
    __shared__ ull   red2[NB][TPB];        // packed (x2, xy) partials   32 KB
    __shared__ float red1[NB][TPB / 2];    // y2 partials (pre-folded)    8 KB
    __shared__ ull   sb[2][NB][R_];        // 0.1*loraB rows, dup'd       2 KB
    __shared__ int   sidx[2][NB];
    __shared__ ull   scx[NB], scy[NB];

    const int tid  = threadIdx.x;
    const int wid  = tid >> 5;
    const int lane = tid & 31;
    const int d0   = tid * 2;

    // lora_A register-resident: lane owns A[r][d0:d0+2] for all 16 ranks
    ull a[R_];
    #pragma unroll
    for (int r = 0; r < R_; ++r)
        a[r] = __ldg(reinterpret_cast<const ull*>(loraA + r * D_ + d0));

    const int S  = gridDim.x;
    const int b0 = blockIdx.x;

    // ---------------- prologue ----------------
    ull xc[NB];
    {
        const int g0 = b0 * NB;
        #pragma unroll
        for (int row = 0; row < NB; ++row) {
            int g = g0 + row;
            if (g < n_rows) {
                int idx = __ldg(indices + g);
                xc[row] = __ldg(reinterpret_cast<const ull*>(baseW + (size_t)idx * D_ + d0));
            } else xc[row] = 0ull;
        }
        if (tid < NB) {
            int gB = (b0 + S) * NB + tid;
            sidx[1][tid] = ((b0 + S) < nbatch && gB < n_rows) ? __ldg(indices + gB) : -1;
        }
        if (tid < NB * R_) {
            int row = tid >> 4, r = tid & 15;
            int g = g0 + row;
            if (g < n_rows) {
                int idx = __ldg(indices + g);
                sb[0][row][r] = dup_(0.1f * __ldg(loraB + (size_t)idx * R_ + r));
            } else sb[0][row][r] = 0ull;
        }
    }
    __syncthreads();

    int buf = 0;
    for (int B = b0; B < nbatch; B += S, buf ^= 1) {

        // ---- step a: prefetch next batch (x -> regs, b/idx -> smem) ----
        ull xn[NB];
        const bool havenext = (B + S) < nbatch;
        #pragma unroll
        for (int row = 0; row < NB; ++row) {
            int idx = havenext ? sidx[buf ^ 1][row] : -1;
            xn[row] = (idx >= 0)
                ? __ldg(reinterpret_cast<const ull*>(baseW + (size_t)idx * D_ + d0))
                : 0ull;
        }
        if (tid < NB) {
            long long gB = (long long)(B + 2 * S) * NB + tid;
            sidx[buf][tid] = ((B + 2 * S) < nbatch && gB < n_rows)
                             ? __ldg(indices + gB) : -1;
        }
        if (tid < NB * R_) {
            int row = tid >> 4, r = tid & 15;
            int idx = havenext ? sidx[buf ^ 1][row] : -1;
            sb[buf ^ 1][row][r] = (idx >= 0)
                ? dup_(0.1f * __ldg(loraB + (size_t)idx * R_ + r)) : 0ull;
        }

        // ---- step b: delta + partials for current batch ----
        ull dv[NB];
        #pragma unroll
        for (int row = 0; row < NB; ++row) {
            const ulonglong2* bp = reinterpret_cast<const ulonglong2*>(sb[buf][row]);
            ulonglong2 b01 = bp[0];
            ull acc0 = fmul2(b01.x, a[0]);
            ull acc1 = fmul2(b01.y, a[1]);
            #pragma unroll
            for (int k = 1; k < R_ / 2; ++k) {
                ulonglong2 b = bp[k];
                acc0 = ffma2(b.x, a[2 * k],     acc0);
                acc1 = ffma2(b.y, a[2 * k + 1], acc1);
            }
            dv[row] = fadd2(acc0, acc1);

            float xl = lo_(xc[row]), xh = hi_(xc[row]);
            float yl = lo_(dv[row]), yh = hi_(dv[row]);
            float x2p = fmaf(xl, xl, xh * xh);
            float xyp = fmaf(xl, yl, xh * yh);
            float y2p = fmaf(yl, yl, yh * yh);
            red2[row][tid] = pack2_(x2p, xyp);
            y2p += __shfl_xor_sync(0xffffffffu, y2p, 16);
            if (lane < 16) red1[row][wid * 16 + lane] = y2p;
        }
        __syncthreads();

        // ---- step e: warp w reduces row w (packed trees) + epilogue ----
        if (wid < NB) {
            const ull* p2 = red2[wid];
            ull sp = p2[lane];
            #pragma unroll
            for (int k = 1; k < TPB / 32; ++k) sp = fadd2(sp, p2[lane + k * 32]);
            float s2 = 0.f;
            #pragma unroll
            for (int k = 0; k < TPB / 64; ++k) s2 += red1[wid][lane + k * 32];
            #pragma unroll
            for (int off = 16; off > 0; off >>= 1) {
                sp = fadd2(sp, __shfl_xor_sync(0xffffffffu, sp, off));
                s2 += __shfl_xor_sync(0xffffffffu, s2, off);
            }
            if (lane == 0) {
                const float MAXN = 1.0f - 1e-5f;
                const float EPSN = 1e-5f;
                float x2 = lo_(sp);
                float xy = hi_(sp);
                float y2 = s2;

                float nx = sqrtf(x2);
                float sx = (nx > MAXN) ? __fdividef(MAXN, fmaxf(nx, EPSN)) : 1.0f;
                float ny = sqrtf(y2);
                float sy = (ny > MAXN) ? __fdividef(MAXN, fmaxf(ny, EPSN)) : 1.0f;

                float X2 = sx * sx * x2;
                float Y2 = sy * sy * y2;
                float XY = sx * sy * xy;

                float A_  = 1.0f + 2.0f * XY + Y2;
                float B_  = 1.0f - X2;
                float den = fmaxf(1.0f + 2.0f * XY + X2 * Y2, 1e-15f);

                float n2 = (A_ * A_ * X2 + 2.0f * A_ * B_ * XY + B_ * B_ * Y2)
                           / (den * den);
                float no = sqrtf(fmaxf(n2, 0.0f));
                float sf = (no > MAXN) ? __fdividef(MAXN, fmaxf(no, EPSN)) : 1.0f;

                float cx = __fdividef(sf * A_ * sx, den);
                float cy = __fdividef(sf * B_ * sy, den);
                scx[wid] = dup_(cx);
                scy[wid] = dup_(cy);
            }
        }
        __syncthreads();

        // ---- stores + rotate ----
        const int row0 = B * NB;
        #pragma unroll
        for (int row = 0; row < NB; ++row) {
            int g = row0 + row;
            if (g < n_rows) {
                ull o = ffma2(scx[row], xc[row], fmul2(scy[row], dv[row]));
                __stcs(reinterpret_cast<ull*>(out + (size_t)g * D_ + d0), o);
            }
        }
        #pragma unroll
        for (int row = 0; row < NB; ++row) xc[row] = xn[row];
    }
}

extern "C" void kernel_launch(void* const* d_in, const int* in_sizes, int n_in,
                              void* d_out, int out_size)
{
    const int*   indices = (const int*)  d_in[0];
    const float* baseW   = (const float*)d_in[1];
    const float* loraA   = (const float*)d_in[2];
    const float* loraB   = (const float*)d_in[3];
    float*       out     = (float*)d_out;

    int n_rows = in_sizes[0];                    // 32768
    int nbatch = (n_rows + NB - 1) / NB;         // 4096
    int grid   = nbatch < 148 ? nbatch : 148;    // persistent: 1 CTA/SM

    rlora_kernel<<<grid, TPB>>>(indices, baseW, loraA, loraB, out, n_rows, nbatch);
}